// round 14
// baseline (speedup 1.0000x reference)
#include <cuda_runtime.h>

#define NB    4096
#define NPOSE 13
#define NHID  256
#define NIN   269
#define NCTX  256
#define BT    28      // batch rows per CTA
#define NTHR  512     // two halves: half 0 -> rows 0..15 (4 q), half 1 -> rows 16..27 (3 q)

// Input-layer weights duplicated (tiny: 13 k-iters + one-time 256 k-iters).
__device__ float2 g_Wptd[NPOSE * NHID];          // W_in pose part: [k][j] -> (w,w)
__device__ float2 g_Wctd[NCTX  * NHID];          // W_in ctx  part: [k][j] -> (w,w)
// Gate weights PACKED, non-duplicated: 2 LDGs per k per thread.
__device__ float4 g_W4[NHID * NHID];             // [k][j] -> (w_ir, w_iz, w_in, w_hr)
__device__ float2 g_W2[NHID * NHID];             // [k][j] -> (w_hz, w_hn)

// Packed dual-fp32 FMA (Blackwell f32x2 pipe; only reachable via PTX).
__device__ __forceinline__ float2 ffma2(float2 a, float2 b, float2 c) {
    float2 d;
    asm("fma.rn.f32x2 %0, %1, %2, %3;"
        : "=l"(*reinterpret_cast<unsigned long long*>(&d))
        : "l"(*reinterpret_cast<unsigned long long*>(&a)),
          "l"(*reinterpret_cast<unsigned long long*>(&b)),
          "l"(*reinterpret_cast<unsigned long long*>(&c)));
    return d;
}

__device__ __forceinline__ float sigm(float a) {
    return 1.0f / (1.0f + __expf(-a));
}
__device__ __forceinline__ float tanh_acc(float a) {
    float e = __expf(-2.0f * fabsf(a));      // e in (0,1], overflow-safe
    float t = (1.0f - e) / (1.0f + e);
    return copysignf(t, a);
}

__global__ void prep_kernel(const float* __restrict__ W_in,
                            const float* __restrict__ W_ih,
                            const float* __restrict__ W_hh) {
    int i = blockIdx.x * blockDim.x + threadIdx.x;
    if (i < NPOSE * NHID) {
        int k = i / NHID, j = i % NHID;
        float w = W_in[j * NIN + k];
        g_Wptd[i] = make_float2(w, w);
    }
    if (i < NCTX * NHID) {
        int k = i / NHID, j = i % NHID;
        float w = W_in[j * NIN + NPOSE + k];
        g_Wctd[i] = make_float2(w, w);
    }
    if (i < NHID * NHID) {
        int k = i / NHID, j = i % NHID;
        g_W4[i] = make_float4(W_ih[(size_t)(0 * NHID + j) * NHID + k],
                              W_ih[(size_t)(1 * NHID + j) * NHID + k],
                              W_ih[(size_t)(2 * NHID + j) * NHID + k],
                              W_hh[(size_t)(0 * NHID + j) * NHID + k]);
        g_W2[i] = make_float2(W_hh[(size_t)(1 * NHID + j) * NHID + k],
                              W_hh[(size_t)(2 * NHID + j) * NHID + k]);
    }
}

// Dense input GEMM column for unit j over this half's rows (duplicated weights).
template<int NQH, int QOFF>
__device__ __forceinline__ void gemm_in(const float2* __restrict__ Wd, int nk,
                                        const float* __restrict__ src, int j,
                                        float2* ax)
{
    #pragma unroll 4
    for (int k = 0; k < nk; k++) {
        float2 w2 = Wd[k * NHID + j];
        const float4* pr = reinterpret_cast<const float4*>(src + k * BT) + QOFF;
        #pragma unroll
        for (int q = 0; q < NQH; q++) {
            float4 v = pr[q];
            ax[2*q]   = ffma2(make_float2(v.x, v.y), w2, ax[2*q]);
            ax[2*q+1] = ffma2(make_float2(v.z, v.w), w2, ax[2*q+1]);
        }
    }
}

// Gate-GEMM accumulation over k in [k0, k1). Unroll-4 lets ptxas front-batch
// the weight LDGs (MLP ~8) to cover L2 latency; no manual prefetch needed.
template<int NQH, int QOFF>
__device__ __forceinline__ void gru_accum(int k0, int k1,
                                          const float* __restrict__ s_x,
                                          const float* __restrict__ hprev,
                                          int j,
                                          float2* ar, float2* az,
                                          float2* ani, float2* anh)
{
    #pragma unroll 4
    for (int k = k0; k < k1; k++) {
        float4 wa = g_W4[(size_t)k * NHID + j];   // lane-coalesced LDG.128
        float2 wb = g_W2[(size_t)k * NHID + j];   // lane-coalesced LDG.64

        // duplicate to lane pairs on the alu pipe (fma pipe untouched)
        float2 wir = make_float2(wa.x, wa.x);
        float2 wiz = make_float2(wa.y, wa.y);
        float2 win = make_float2(wa.z, wa.z);
        float2 whr = make_float2(wa.w, wa.w);
        float2 whz = make_float2(wb.x, wb.x);
        float2 whn = make_float2(wb.y, wb.y);

        const float4* xr = reinterpret_cast<const float4*>(s_x   + k * BT) + QOFF;
        const float4* hr = reinterpret_cast<const float4*>(hprev + k * BT) + QOFF;
        #pragma unroll
        for (int q = 0; q < NQH; q++) {
            float4 xv = xr[q];                 // LDS.128 broadcast (conflict-free)
            float4 hv = hr[q];
            float2 x0 = make_float2(xv.x, xv.y), x1 = make_float2(xv.z, xv.w);
            float2 h0 = make_float2(hv.x, hv.y), h1 = make_float2(hv.z, hv.w);
            ar [2*q]   = ffma2(x0, wir, ar [2*q]);
            ar [2*q]   = ffma2(h0, whr, ar [2*q]);
            ar [2*q+1] = ffma2(x1, wir, ar [2*q+1]);
            ar [2*q+1] = ffma2(h1, whr, ar [2*q+1]);
            az [2*q]   = ffma2(x0, wiz, az [2*q]);
            az [2*q]   = ffma2(h0, whz, az [2*q]);
            az [2*q+1] = ffma2(x1, wiz, az [2*q+1]);
            az [2*q+1] = ffma2(h1, whz, az [2*q+1]);
            ani[2*q]   = ffma2(x0, win, ani[2*q]);
            ani[2*q+1] = ffma2(x1, win, ani[2*q+1]);
            anh[2*q]   = ffma2(h0, whn, anh[2*q]);
            anh[2*q+1] = ffma2(h1, whn, anh[2*q+1]);
        }
    }
}

// Phase B (six gate GEMM columns) + Phase C (GRU pointwise), unit j, this half's rows.
// KS desynchronizes the two halves' k-order (half1 starts at k=128) to smooth
// the L1tex queue; fp32 accumulation order change is numerically harmless.
template<int NQH, int QOFF, int KS>
__device__ __forceinline__ void gru_step(const float* __restrict__ s_x,
                                         const float* __restrict__ hprev,
                                         float*       __restrict__ hnext,
                                         int j,
                                         float brz0, float brz1,
                                         float bin_, float bhn)
{
    constexpr int NP = 2 * NQH;
    float2 ar[NP], az[NP], ani[NP], anh[NP];
    #pragma unroll
    for (int p = 0; p < NP; p++) {
        ar[p] = make_float2(0.f, 0.f);
        az[p] = ar[p]; ani[p] = ar[p]; anh[p] = ar[p];
    }

    gru_accum<NQH, QOFF>(KS, NHID, s_x, hprev, j, ar, az, ani, anh);
    if (KS > 0)
        gru_accum<NQH, QOFF>(0, KS, s_x, hprev, j, ar, az, ani, anh);

    // GRU pointwise, registers only
    const float2* hop = reinterpret_cast<const float2*>(hprev + j * BT) + QOFF * 2;
    float2*       hnp = reinterpret_cast<float2*>(hnext + j * BT) + QOFF * 2;
    #pragma unroll
    for (int p = 0; p < NP; p++) {
        float2 ho = hop[p];
        float rr = sigm(ar[p].x + brz0);
        float zz = sigm(az[p].x + brz1);
        float nn = tanh_acc(ani[p].x + bin_ + rr * (anh[p].x + bhn));
        float hx = (1.0f - zz) * nn + zz * ho.x;
        rr = sigm(ar[p].y + brz0);
        zz = sigm(az[p].y + brz1);
        nn = tanh_acc(ani[p].y + bin_ + rr * (anh[p].y + bhn));
        float hy = (1.0f - zz) * nn + zz * ho.y;
        hnp[p] = make_float2(hx, hy);
    }
}

__global__ __launch_bounds__(NTHR, 1)
void rnn_kernel(const float* __restrict__ last_pose,
                const float* __restrict__ context,
                const int*   __restrict__ d_nf,
                const float* __restrict__ b_in,
                const float* __restrict__ b_ih,
                const float* __restrict__ b_hh,
                const float* __restrict__ W_out,
                const float* __restrict__ b_out,
                float*       __restrict__ out)
{
    extern __shared__ float sm[];
    float* s_cb   = sm;                     // [256][28]  c_base = Wc@ctx + b_in
    float* s_x    = s_cb  + NHID * BT;      // [256][28]  x (temp: raw ctx at init)
    float* s_h0   = s_x   + NHID * BT;      // [256][28]  h ping
    float* s_h1   = s_h0  + NHID * BT;      // [256][28]  h pong
    float* s_pose = s_h1  + NHID * BT;      // [16][28]   pose (13 used)

    const int tid  = threadIdx.x;
    const int j    = tid & (NHID - 1);      // hidden unit owned by this thread
    const int half = tid >> 8;              // 0: rows 0..15 (4 q), 1: rows 16..27 (3 q)
    const int r0   = half * 16;
    const int nr   = half ? 12 : 16;
    const int row0 = blockIdx.x * BT;
    const int nf   = d_nf[0];

    // --- init: raw ctx -> s_x (transposed), h=0; pose -> s_pose ---
    for (int rr = 0; rr < nr; rr++) {
        int r = r0 + rr;
        int grow = row0 + r; if (grow > NB - 1) grow = NB - 1;   // clamp pad rows
        s_x [j * BT + r] = context[(size_t)grow * NCTX + j];
        s_h0[j * BT + r] = 0.0f;
    }
    if (tid < NPOSE * BT) {
        int p = tid / BT, r = tid - p * BT;
        int grow = row0 + r; if (grow > NB - 1) grow = NB - 1;
        s_pose[p * BT + r] = last_pose[(size_t)grow * NPOSE + p];
    }
    const float binj = b_in[j];
    const float brz0 = b_ih[j]        + b_hh[j];          // fused r bias
    const float brz1 = b_ih[NHID + j] + b_hh[NHID + j];   // fused z bias
    const float bin_ = b_ih[2 * NHID + j];
    const float bhn  = b_hh[2 * NHID + j];
    __syncthreads();

    // --- precompute c_base = Wc @ ctx + b_in (hoisted out of the time loop) ---
    {
        float2 cb[8];
        if (half == 0) {
            #pragma unroll
            for (int p = 0; p < 8; p++) cb[p] = make_float2(binj, binj);
            gemm_in<4, 0>(g_Wctd, NCTX, s_x, j, cb);
            float2* co = reinterpret_cast<float2*>(s_cb + j * BT);
            #pragma unroll
            for (int p = 0; p < 8; p++) co[p] = cb[p];
        } else {
            #pragma unroll
            for (int p = 0; p < 6; p++) cb[p] = make_float2(binj, binj);
            gemm_in<3, 4>(g_Wctd, NCTX, s_x, j, cb);
            float2* co = reinterpret_cast<float2*>(s_cb + j * BT) + 8;
            #pragma unroll
            for (int p = 0; p < 6; p++) co[p] = cb[p];
        }
    }
    __syncthreads();

    for (int t = 0; t < nf; t++) {
        const float* hprev = (t & 1) ? s_h1 : s_h0;
        float*       hnext = (t & 1) ? s_h0 : s_h1;

        // ---- Phase A: x = relu(c_base + Wp @ pose), only 13 k-iterations ----
        if (half == 0) {
            float2 ax[8];
            const float2* cb = reinterpret_cast<const float2*>(s_cb + j * BT);
            #pragma unroll
            for (int p = 0; p < 8; p++) ax[p] = cb[p];
            gemm_in<4, 0>(g_Wptd, NPOSE, s_pose, j, ax);
            float2* xo = reinterpret_cast<float2*>(s_x + j * BT);
            #pragma unroll
            for (int p = 0; p < 8; p++)
                xo[p] = make_float2(fmaxf(ax[p].x, 0.0f), fmaxf(ax[p].y, 0.0f));
        } else {
            float2 ax[6];
            const float2* cb = reinterpret_cast<const float2*>(s_cb + j * BT) + 8;
            #pragma unroll
            for (int p = 0; p < 6; p++) ax[p] = cb[p];
            gemm_in<3, 4>(g_Wptd, NPOSE, s_pose, j, ax);
            float2* xo = reinterpret_cast<float2*>(s_x + j * BT) + 8;
            #pragma unroll
            for (int p = 0; p < 6; p++)
                xo[p] = make_float2(fmaxf(ax[p].x, 0.0f), fmaxf(ax[p].y, 0.0f));
        }
        __syncthreads();

        // ---- Phase B + C: gate GEMMs + GRU pointwise (k-desynced halves) ----
        if (half == 0) gru_step<4, 0, 0>  (s_x, hprev, hnext, j, brz0, brz1, bin_, bhn);
        else           gru_step<3, 4, 128>(s_x, hprev, hnext, j, brz0, brz1, bin_, bhn);
        __syncthreads();

        // ---- Phase D (fused): pose delta + quaternion normalize via shuffles ----
        // Lane map: r = tid>>4 (0..27), p = tid&15. A row's quaternion components
        // sit in one 16-lane group -> shfl replaces the smem round-trip.
        if (tid < BT * 16) {                  // 448 threads = warps 0..13 (full warps)
            int r = tid >> 4, p = tid & 15;
            int pc = (p < 13) ? p : 12;       // dummy lanes compute harmlessly
            const float4* wo = reinterpret_cast<const float4*>(W_out + pc * NHID);
            float a0 = b_out[pc], a1 = 0.f, a2 = 0.f, a3 = 0.f;
            #pragma unroll 4
            for (int k4 = 0; k4 < NHID / 4; k4++) {
                float4 w4 = wo[k4];
                int kb = k4 * 4;
                a0 = fmaf(hnext[(kb    ) * BT + r], w4.x, a0);
                a1 = fmaf(hnext[(kb + 1) * BT + r], w4.y, a1);
                a2 = fmaf(hnext[(kb + 2) * BT + r], w4.z, a2);
                a3 = fmaf(hnext[(kb + 3) * BT + r], w4.w, a3);
            }
            float raw = s_pose[pc * BT + r] + ((a0 + a1) + (a2 + a3));

            int lane = tid & 31;
            int base = lane & 0x10;           // 16-lane group of this row
            float q3 = __shfl_sync(0xFFFFFFFFu, raw, base + 3);
            float q4 = __shfl_sync(0xFFFFFFFFu, raw, base + 4);
            float q5 = __shfl_sync(0xFFFFFFFFu, raw, base + 5);
            float q6 = __shfl_sync(0xFFFFFFFFu, raw, base + 6);
            float v = raw;
            if (p >= 3 && p <= 6) {
                float nrm = fmaxf(sqrtf(q3*q3 + q4*q4 + q5*q5 + q6*q6), 1e-12f);
                v = raw / nrm;
            }
            if (p < 13) {
                s_pose[p * BT + r] = v;
                int grow = row0 + r;
                if (grow < NB)
                    out[((size_t)grow * nf + t) * NPOSE + p] = v;
            }
        }
        __syncthreads();
    }
}

extern "C" void kernel_launch(void* const* d_in, const int* in_sizes, int n_in,
                              void* d_out, int out_size) {
    const float* last_pose = (const float*)d_in[0];
    const float* context   = (const float*)d_in[1];
    const int*   num_fut   = (const int*)  d_in[2];
    const float* W_in      = (const float*)d_in[3];
    const float* b_in      = (const float*)d_in[4];
    const float* W_ih      = (const float*)d_in[5];
    const float* b_ih      = (const float*)d_in[6];
    const float* W_hh      = (const float*)d_in[7];
    const float* b_hh      = (const float*)d_in[8];
    const float* W_out     = (const float*)d_in[9];
    const float* b_out     = (const float*)d_in[10];
    float* out = (float*)d_out;

    // packed weight transposes (L2-resident, deterministic each call)
    prep_kernel<<<(NHID * NHID + 255) / 256, 256>>>(W_in, W_ih, W_hh);

    const int smem_bytes = (4 * NHID * BT + 16 * BT) * (int)sizeof(float);
    cudaFuncSetAttribute(rnn_kernel,
                         cudaFuncAttributeMaxDynamicSharedMemorySize, smem_bytes);

    const int grid = (NB + BT - 1) / BT;   // 147 CTAs -> one wave
    rnn_kernel<<<grid, NTHR, smem_bytes>>>(last_pose, context, num_fut,
                                           b_in, b_ih, b_hh, W_out, b_out, out);
}